// round 1
// baseline (speedup 1.0000x reference)
#include <cuda_runtime.h>
#include <math.h>

#define BATCH 4
#define TSEQ 501
#define MROWS (BATCH*TSEQ)   /* 2004 */
#define DM 256
#define DI 512
#define NSTATE 16

/* ---------------- persistent scratch (no allocs allowed) ---------------- */
__device__ __align__(256) float g_X    [MROWS*DM];
__device__ __align__(256) float g_XN   [MROWS*DM];
__device__ __align__(256) float g_TMP  [MROWS*1024];
__device__ __align__(256) float g_XC   [MROWS*DI];
__device__ __align__(256) float g_T2   [MROWS*1024];
__device__ __align__(256) float g_XM   [MROWS*DI];
__device__ __align__(256) float g_PROJ [MROWS*64];
__device__ __align__(256) float g_DELTA[MROWS*DI];
__device__ __align__(256) float g_YM   [MROWS*DI];
__device__ __align__(256) float g_YF   [MROWS*DI];
__device__ __align__(256) float g_YB   [MROWS*DI];
__device__ __align__(256) float g_G    [MROWS*1024];

/* ---------------- patch embedding: conv1d k=10 stride=10 ---------------- */
#define PPT 6
__global__ void __launch_bounds__(256) patch_kernel(const float* __restrict__ x,
                                                    const float* __restrict__ pw,
                                                    const float* __restrict__ pb)
{
    __shared__ float xs[129*PPT*10];   /* input slab for PPT patches   */
    __shared__ float ws[256*10];       /* weights for one input channel */
    const int bb  = blockIdx.y;
    const int pp0 = blockIdx.x * PPT;
    const int tid = threadIdx.x;
    const int t0  = pp0 * 10;

    for (int e = tid; e < 129*PPT*10; e += 256) {
        int i   = e / (PPT*10);
        int off = e - i*(PPT*10);
        int ta  = t0 + off;
        xs[e] = (ta < 5000) ? x[((size_t)bb*129 + i)*5000 + ta] : 0.f;
    }

    const int c = tid;
    float acc[PPT];
#pragma unroll
    for (int p = 0; p < PPT; p++) acc[p] = pb[c];

    for (int i = 0; i < 129; i++) {
        __syncthreads();
        for (int e = tid; e < 2560; e += 256) {
            int cc = e / 10;
            int kk = e - cc*10;
            ws[e] = pw[(size_t)cc*1290 + i*10 + kk];
        }
        __syncthreads();
#pragma unroll
        for (int k = 0; k < 10; k++) {
            float wv = ws[c*10 + k];
            const float* xrow = &xs[i*(PPT*10) + k];
#pragma unroll
            for (int p = 0; p < PPT; p++)
                acc[p] = fmaf(wv, xrow[p*10], acc[p]);
        }
    }
#pragma unroll
    for (int p = 0; p < PPT; p++) {
        int pp = pp0 + p;
        if (pp < 500)
            g_X[((size_t)bb*TSEQ + 1 + pp)*DM + c] = acc[p];
    }
}

__global__ void cls_kernel(const float* __restrict__ cls)
{
    int tid = threadIdx.x;            /* 1024 threads */
    int b = tid >> 8, c = tid & 255;
    g_X[((size_t)b*TSEQ)*DM + c] = cls[c];
}

/* ---------------- layernorm over 256 (warp per row) ---------------- */
__global__ void ln_kernel(const float* __restrict__ Xin,
                          const float* __restrict__ g,
                          const float* __restrict__ bt,
                          float* __restrict__ Out, int rows)
{
    int warp = (blockIdx.x * blockDim.x + threadIdx.x) >> 5;
    int lane = threadIdx.x & 31;
    if (warp >= rows) return;
    const float* xr = Xin + (size_t)warp*DM;
    float v[8], s = 0.f, ss = 0.f;
#pragma unroll
    for (int i = 0; i < 8; i++) {
        v[i] = xr[lane + i*32];
        s += v[i];
        ss = fmaf(v[i], v[i], ss);
    }
#pragma unroll
    for (int o = 16; o; o >>= 1) {
        s  += __shfl_xor_sync(0xffffffffu, s,  o);
        ss += __shfl_xor_sync(0xffffffffu, ss, o);
    }
    float mean = s * (1.f/256.f);
    float var  = ss * (1.f/256.f) - mean*mean;
    float inv  = rsqrtf(var + 1e-5f);
    float* orow = Out + (size_t)warp*DM;
#pragma unroll
    for (int i = 0; i < 8; i++) {
        int c = lane + i*32;
        orow[c] = (v[i]-mean)*inv*g[c] + bt[c];
    }
}

/* ---------------- causal depthwise conv (K=4) + silu ---------------- */
__global__ void conv_silu_kernel(const float* __restrict__ src, int srcLd,
                                 const float* __restrict__ cw,
                                 const float* __restrict__ cb,
                                 float* __restrict__ dst)
{
    int idx = blockIdx.x*blockDim.x + threadIdx.x;
    if (idx >= MROWS*DI) return;
    int d = idx & 511;
    int r = idx >> 9;
    int t = r % TSEQ;
    int b = r / TSEQ;
    const float* base = src + ((size_t)b*TSEQ)*srcLd + d;
    float acc = cb[d];
    float w0 = cw[d*4+0], w1 = cw[d*4+1], w2 = cw[d*4+2], w3 = cw[d*4+3];
    if (t >= 3) acc = fmaf(w0, base[(size_t)(t-3)*srcLd], acc);
    if (t >= 2) acc = fmaf(w1, base[(size_t)(t-2)*srcLd], acc);
    if (t >= 1) acc = fmaf(w2, base[(size_t)(t-1)*srcLd], acc);
    acc = fmaf(w3, base[(size_t)t*srcLd], acc);
    dst[(size_t)r*DI + d] = acc / (1.f + __expf(-acc));
}

/* ---------------- generic tiled fp32 GEMM: C = act(A@W^T + bias) (+res) ----
 * A: M x K (row-major, lda), W: N x K (row-major), C: M x N (ldc)
 * flipA/flipC: flip row index within each batch of TSEQ rows
 * act: 0 none, 1 softplus
 */
__global__ void __launch_bounds__(256) gemm_kernel(
    const float* __restrict__ A, int lda,
    const float* __restrict__ W,
    float* __restrict__ C, int ldc,
    const float* __restrict__ bias,
    const float* __restrict__ res,
    int Mm, int Nn, int K,
    int act, int flipA, int flipC)
{
    __shared__ float As[16][128];
    __shared__ float Bs[16][64];
    const int tid = threadIdx.x;
    const int r0 = blockIdx.y * 128;
    const int c0 = blockIdx.x * 64;
    const int tm = tid & 15;      /* 8 rows per thread  */
    const int tn = tid >> 4;      /* 4 cols per thread  */
    const int a4 = tid & 3;       /* which float4 in k  */
    const int ar = tid >> 2;      /* 0..63              */

    const float* aptr0 = nullptr;
    const float* aptr1 = nullptr;
    {
        int grow = r0 + ar;
        if (grow < Mm) {
            int sr = grow;
            if (flipA) { int bb = grow / TSEQ; int tt = grow - bb*TSEQ; sr = bb*TSEQ + (TSEQ-1-tt); }
            aptr0 = A + (size_t)sr*lda + a4*4;
        }
        grow = r0 + ar + 64;
        if (grow < Mm) {
            int sr = grow;
            if (flipA) { int bb = grow / TSEQ; int tt = grow - bb*TSEQ; sr = bb*TSEQ + (TSEQ-1-tt); }
            aptr1 = A + (size_t)sr*lda + a4*4;
        }
    }
    const float* wptr = W + (size_t)(c0 + ar)*K + a4*4;

    float4 pa0 = aptr0 ? *(const float4*)(aptr0) : make_float4(0,0,0,0);
    float4 pa1 = aptr1 ? *(const float4*)(aptr1) : make_float4(0,0,0,0);
    float4 pw  = *(const float4*)(wptr);

    float acc[8][4];
#pragma unroll
    for (int i = 0; i < 8; i++)
#pragma unroll
        for (int j = 0; j < 4; j++) acc[i][j] = 0.f;

    for (int k0 = 0; k0 < K; k0 += 16) {
        __syncthreads();
        As[a4*4+0][ar]    = pa0.x; As[a4*4+1][ar]    = pa0.y;
        As[a4*4+2][ar]    = pa0.z; As[a4*4+3][ar]    = pa0.w;
        As[a4*4+0][ar+64] = pa1.x; As[a4*4+1][ar+64] = pa1.y;
        As[a4*4+2][ar+64] = pa1.z; As[a4*4+3][ar+64] = pa1.w;
        Bs[a4*4+0][ar]    = pw.x;  Bs[a4*4+1][ar]    = pw.y;
        Bs[a4*4+2][ar]    = pw.z;  Bs[a4*4+3][ar]    = pw.w;
        __syncthreads();
        if (k0 + 16 < K) {  /* prefetch next tile into regs, overlaps compute */
            pa0 = aptr0 ? *(const float4*)(aptr0 + k0 + 16) : make_float4(0,0,0,0);
            pa1 = aptr1 ? *(const float4*)(aptr1 + k0 + 16) : make_float4(0,0,0,0);
            pw  = *(const float4*)(wptr + k0 + 16);
        }
#pragma unroll
        for (int kk = 0; kk < 16; kk++) {
            float4 b4 = *(const float4*)&Bs[kk][tn*4];
            float4 a0 = *(const float4*)&As[kk][tm*8];
            float4 a1 = *(const float4*)&As[kk][tm*8+4];
            float av[8] = {a0.x,a0.y,a0.z,a0.w,a1.x,a1.y,a1.z,a1.w};
            float bv[4] = {b4.x,b4.y,b4.z,b4.w};
#pragma unroll
            for (int i = 0; i < 8; i++)
#pragma unroll
                for (int j = 0; j < 4; j++)
                    acc[i][j] = fmaf(av[i], bv[j], acc[i][j]);
        }
    }

#pragma unroll
    for (int i = 0; i < 8; i++) {
        int row = r0 + tm*8 + i;
        if (row >= Mm) continue;
        int srow = row;
        if (flipC) { int bb = row / TSEQ; int tt = row - bb*TSEQ; srow = bb*TSEQ + (TSEQ-1-tt); }
        float* crow = C + (size_t)srow*ldc;
        const float* rrow = res ? res + (size_t)srow*ldc : nullptr;
#pragma unroll
        for (int j = 0; j < 4; j++) {
            int col = c0 + tn*4 + j;
            float v = acc[i][j];
            if (bias) v += bias[col];
            if (act == 1) v = fmaxf(v, 0.f) + log1pf(__expf(-fabsf(v)));  /* softplus */
            if (rrow) v += rrow[col];
            crow[col] = v;
        }
    }
}

/* ---------------- selective scan: thread per (b,d,n) state ---------------- */
__global__ void __launch_bounds__(128) scan_kernel(const float* __restrict__ Al,
                                                   const float* __restrict__ Dp)
{
    const int b   = blockIdx.x;
    const int tid = threadIdx.x;
    const int dl  = tid >> 4;
    const int n   = tid & 15;
    const int d   = blockIdx.y*8 + dl;

    const float Adn = -__expf(Al[d*NSTATE + n]);
    const float Dpd = Dp[d];
    float h = 0.f;

    const float* dptr = g_DELTA + (size_t)b*TSEQ*DI + d;
    const float* uptr = g_XM    + (size_t)b*TSEQ*DI + d;
    const float* pptr = g_PROJ  + (size_t)b*TSEQ*64;
    const float* zptr = g_T2    + (size_t)b*TSEQ*1024 + 512 + d;
    float*       yptr = g_YM    + (size_t)b*TSEQ*DI + d;

    for (int t = 0; t < TSEQ; t++) {
        float delta = dptr[(size_t)t*DI];
        float u     = uptr[(size_t)t*DI];
        float Bm    = pptr[t*64 + 32 + n];
        float Cc    = pptr[t*64 + 48 + n];
        float dA    = __expf(delta * Adn);
        h = fmaf(dA, h, delta * Bm * u);
        float v = h * Cc;
        v += __shfl_xor_sync(0xffffffffu, v, 1);
        v += __shfl_xor_sync(0xffffffffu, v, 2);
        v += __shfl_xor_sync(0xffffffffu, v, 4);
        v += __shfl_xor_sync(0xffffffffu, v, 8);
        if (n == 0) {
            float z = zptr[(size_t)t*1024];
            float y = fmaf(u, Dpd, v);
            yptr[(size_t)t*DI] = y * (z / (1.f + __expf(-z)));
        }
    }
}

/* ---------------- gate + concat: G = [yf*silu(res), yb*silu(res)] ---------- */
__global__ void gate_kernel()
{
    int idx = blockIdx.x*blockDim.x + threadIdx.x;
    if (idx >= MROWS*DI) return;
    int d = idx & 511;
    int r = idx >> 9;
    float rv = g_TMP[(size_t)r*1024 + 512 + d];
    float gate = rv / (1.f + __expf(-rv));
    g_G[(size_t)r*1024 + d]       = g_YF[(size_t)r*DI + d] * gate;
    g_G[(size_t)r*1024 + 512 + d] = g_YB[(size_t)r*DI + d] * gate;
}

/* ---------------- final LN on the cls row ---------------- */
__global__ void final_kernel(const float* __restrict__ g,
                             const float* __restrict__ bt,
                             float* __restrict__ out)
{
    __shared__ float s1[8], s2[8];
    int b = blockIdx.x;
    int c = threadIdx.x;
    float v = g_X[((size_t)b*TSEQ)*DM + c];
    float s = v, ss = v*v;
#pragma unroll
    for (int o = 16; o; o >>= 1) {
        s  += __shfl_xor_sync(0xffffffffu, s,  o);
        ss += __shfl_xor_sync(0xffffffffu, ss, o);
    }
    int w = c >> 5, l = c & 31;
    if (l == 0) { s1[w] = s; s2[w] = ss; }
    __syncthreads();
    float ts = 0.f, tss = 0.f;
#pragma unroll
    for (int i = 0; i < 8; i++) { ts += s1[i]; tss += s2[i]; }
    float mean = ts * (1.f/256.f);
    float var  = tss * (1.f/256.f) - mean*mean;
    out[b*DM + c] = (v-mean)*rsqrtf(var + 1e-5f)*g[c] + bt[c];
}

/* ======================= host driver ======================= */
extern "C" void kernel_launch(void* const* d_in, const int* in_sizes, int n_in,
                              void* d_out, int out_size)
{
    (void)in_sizes; (void)n_in; (void)out_size;
    const float* x       = (const float*)d_in[0];
    const float* patch_w = (const float*)d_in[1];
    const float* patch_b = (const float*)d_in[2];
    const float* cls_tok = (const float*)d_in[3];
    const float* ln_g    = (const float*)d_in[4];
    const float* ln_b    = (const float*)d_in[5];
    const float* in_w    = (const float*)d_in[6];
    const float* cw      = (const float*)d_in[7];
    const float* cb      = (const float*)d_in[8];
    const float* out_w   = (const float*)d_in[9];
    const float* fn_g    = (const float*)d_in[10];
    const float* fn_b    = (const float*)d_in[11];
    const float* m_in[2]  = {(const float*)d_in[12], (const float*)d_in[21]};
    const float* m_cw[2]  = {(const float*)d_in[13], (const float*)d_in[22]};
    const float* m_cb[2]  = {(const float*)d_in[14], (const float*)d_in[23]};
    const float* m_xp[2]  = {(const float*)d_in[15], (const float*)d_in[24]};
    const float* m_dtw[2] = {(const float*)d_in[16], (const float*)d_in[25]};
    const float* m_dtb[2] = {(const float*)d_in[17], (const float*)d_in[26]};
    const float* m_Al[2]  = {(const float*)d_in[18], (const float*)d_in[27]};
    const float* m_D[2]   = {(const float*)d_in[19], (const float*)d_in[28]};
    const float* m_ow[2]  = {(const float*)d_in[20], (const float*)d_in[29]};

    float *pX, *pXN, *pTMP, *pXC, *pT2, *pXM, *pPROJ, *pDELTA, *pYM, *pYF, *pYB, *pG;
    cudaGetSymbolAddress((void**)&pX,     g_X);
    cudaGetSymbolAddress((void**)&pXN,    g_XN);
    cudaGetSymbolAddress((void**)&pTMP,   g_TMP);
    cudaGetSymbolAddress((void**)&pXC,    g_XC);
    cudaGetSymbolAddress((void**)&pT2,    g_T2);
    cudaGetSymbolAddress((void**)&pXM,    g_XM);
    cudaGetSymbolAddress((void**)&pPROJ,  g_PROJ);
    cudaGetSymbolAddress((void**)&pDELTA, g_DELTA);
    cudaGetSymbolAddress((void**)&pYM,    g_YM);
    cudaGetSymbolAddress((void**)&pYF,    g_YF);
    cudaGetSymbolAddress((void**)&pYB,    g_YB);
    cudaGetSymbolAddress((void**)&pG,     g_G);

    patch_kernel<<<dim3(84, BATCH), 256>>>(x, patch_w, patch_b);
    cls_kernel<<<1, 1024>>>(cls_tok);

    for (int l = 0; l < 8; l++) {
        ln_kernel<<<251, 256>>>(pX, ln_g + l*DM, ln_b + l*DM, pXN, MROWS);
        /* in-proj: (2004x256)@(256x1024) -> TMP; xc=cols[0:512), res=cols[512:1024) */
        gemm_kernel<<<dim3(16, 16), 256>>>(pXN, DM, in_w + (size_t)l*1024*DM, pTMP, 1024,
                                           nullptr, nullptr, MROWS, 1024, DM, 0, 0, 0);
        conv_silu_kernel<<<4008, 256>>>(pTMP, 1024, cw + l*DI*4, cb + l*DI, pXC);

        for (int dir = 0; dir < 2; dir++) {
            /* mamba in-proj (flip A rows for backward direction) */
            gemm_kernel<<<dim3(16, 16), 256>>>(pXC, DI, m_in[dir] + (size_t)l*1024*DI, pT2, 1024,
                                               nullptr, nullptr, MROWS, 1024, DI, 0, dir, 0);
            conv_silu_kernel<<<4008, 256>>>(pT2, 1024, m_cw[dir] + l*DI*4, m_cb[dir] + l*DI, pXM);
            /* x-proj -> [dt(32) | B(16) | C(16)] */
            gemm_kernel<<<dim3(1, 16), 256>>>(pXM, DI, m_xp[dir] + (size_t)l*64*DI, pPROJ, 64,
                                              nullptr, nullptr, MROWS, 64, DI, 0, 0, 0);
            /* dt-proj + softplus */
            gemm_kernel<<<dim3(8, 16), 256>>>(pPROJ, 64, m_dtw[dir] + (size_t)l*DI*32, pDELTA, DI,
                                              m_dtb[dir] + l*DI, nullptr, MROWS, DI, 32, 1, 0, 0);
            /* selective scan + D skip + silu(z) gate -> YM */
            scan_kernel<<<dim3(BATCH, 64), 128>>>(m_Al[dir] + (size_t)l*DI*NSTATE, m_D[dir] + l*DI);
            /* out-proj (un-flip rows on store for backward) */
            gemm_kernel<<<dim3(8, 16), 256>>>(pYM, DI, m_ow[dir] + (size_t)l*DI*DI,
                                              dir ? pYB : pYF, DI,
                                              nullptr, nullptr, MROWS, DI, DI, 0, 0, dir);
        }
        gate_kernel<<<4008, 256>>>();
        /* out-proj + residual: X = G@out_w^T + X */
        gemm_kernel<<<dim3(4, 16), 256>>>(pG, 1024, out_w + (size_t)l*DM*1024, pX, DM,
                                          nullptr, pX, MROWS, DM, 1024, 0, 0, 0);
    }
    final_kernel<<<BATCH, 256>>>(fn_g, fn_b, (float*)d_out);
}

// round 3
// speedup vs baseline: 2.1747x; 2.1747x over previous
#include <cuda_runtime.h>
#include <math.h>

#define BATCH 4
#define TSEQ 501
#define MROWS (BATCH*TSEQ)   /* 2004 */
#define DM 256
#define DI 512
#define NSTATE 16

/* ---------------- persistent scratch (no allocs allowed) ---------------- */
__device__ __align__(256) float g_X    [MROWS*DM];
__device__ __align__(256) float g_XN   [MROWS*DM];
__device__ __align__(256) float g_TMP  [MROWS*1024];
__device__ __align__(256) float g_XC   [MROWS*DI];
__device__ __align__(256) float g_T2   [2][MROWS*1024];
__device__ __align__(256) float g_XM   [2][MROWS*DI];
__device__ __align__(256) float g_PROJ [2][MROWS*64];
__device__ __align__(256) float g_DELTA[2][MROWS*DI];
__device__ __align__(256) float g_YM   [2][MROWS*DI];
__device__ __align__(256) float g_YF   [MROWS*DI];
__device__ __align__(256) float g_YB   [MROWS*DI];
__device__ __align__(256) float g_G    [MROWS*1024];

/* ---------------- per-direction argument bundles ---------------- */
struct GArgs {
    const float* A;
    const float* W;
    float*       C;
    const float* bias;
    const float* res;
    int flipA;
    int flipC;
};

struct CArgs {
    const float* src;
    int          srcLd;
    const float* cw;
    const float* cb;
    float*       dst;
};

/* ---------------- patch embedding: conv1d k=10 stride=10 ---------------- */
#define PPT 6
__global__ void __launch_bounds__(256) patch_kernel(const float* __restrict__ x,
                                                    const float* __restrict__ pw,
                                                    const float* __restrict__ pb)
{
    __shared__ float xs[129*PPT*10];
    __shared__ float ws[256*10];
    const int bb  = blockIdx.y;
    const int pp0 = blockIdx.x * PPT;
    const int tid = threadIdx.x;
    const int t0  = pp0 * 10;

    for (int e = tid; e < 129*PPT*10; e += 256) {
        int i   = e / (PPT*10);
        int off = e - i*(PPT*10);
        int ta  = t0 + off;
        xs[e] = (ta < 5000) ? x[((size_t)bb*129 + i)*5000 + ta] : 0.f;
    }

    const int c = tid;
    float acc[PPT];
#pragma unroll
    for (int p = 0; p < PPT; p++) acc[p] = pb[c];

    for (int i = 0; i < 129; i++) {
        __syncthreads();
        for (int e = tid; e < 2560; e += 256) {
            int cc = e / 10;
            int kk = e - cc*10;
            ws[e] = pw[(size_t)cc*1290 + i*10 + kk];
        }
        __syncthreads();
#pragma unroll
        for (int k = 0; k < 10; k++) {
            float wv = ws[c*10 + k];
            const float* xrow = &xs[i*(PPT*10) + k];
#pragma unroll
            for (int p = 0; p < PPT; p++)
                acc[p] = fmaf(wv, xrow[p*10], acc[p]);
        }
    }
#pragma unroll
    for (int p = 0; p < PPT; p++) {
        int pp = pp0 + p;
        if (pp < 500)
            g_X[((size_t)bb*TSEQ + 1 + pp)*DM + c] = acc[p];
    }
}

__global__ void cls_kernel(const float* __restrict__ cls)
{
    int tid = threadIdx.x;
    int b = tid >> 8, c = tid & 255;
    g_X[((size_t)b*TSEQ)*DM + c] = cls[c];
}

/* ---------------- layernorm over 256 (warp per row) ---------------- */
__global__ void ln_kernel(const float* __restrict__ Xin,
                          const float* __restrict__ g,
                          const float* __restrict__ bt,
                          float* __restrict__ Out, int rows)
{
    int warp = (blockIdx.x * blockDim.x + threadIdx.x) >> 5;
    int lane = threadIdx.x & 31;
    if (warp >= rows) return;
    const float* xr = Xin + (size_t)warp*DM;
    float v[8], s = 0.f, ss = 0.f;
#pragma unroll
    for (int i = 0; i < 8; i++) {
        v[i] = xr[lane + i*32];
        s += v[i];
        ss = fmaf(v[i], v[i], ss);
    }
#pragma unroll
    for (int o = 16; o; o >>= 1) {
        s  += __shfl_xor_sync(0xffffffffu, s,  o);
        ss += __shfl_xor_sync(0xffffffffu, ss, o);
    }
    float mean = s * (1.f/256.f);
    float var  = ss * (1.f/256.f) - mean*mean;
    float inv  = rsqrtf(var + 1e-5f);
    float* orow = Out + (size_t)warp*DM;
#pragma unroll
    for (int i = 0; i < 8; i++) {
        int c = lane + i*32;
        orow[c] = (v[i]-mean)*inv*g[c] + bt[c];
    }
}

/* ---------------- causal depthwise conv (K=4) + silu, dir-batched -------- */
__global__ void conv_silu_kernel(CArgs c0, CArgs c1)
{
    CArgs c = blockIdx.z ? c1 : c0;
    int idx = blockIdx.x*blockDim.x + threadIdx.x;
    if (idx >= MROWS*DI) return;
    int d = idx & 511;
    int r = idx >> 9;
    int t = r % TSEQ;
    int b = r / TSEQ;
    const float* base = c.src + ((size_t)b*TSEQ)*c.srcLd + d;
    float acc = c.cb[d];
    float w0 = c.cw[d*4+0], w1 = c.cw[d*4+1], w2 = c.cw[d*4+2], w3 = c.cw[d*4+3];
    if (t >= 3) acc = fmaf(w0, base[(size_t)(t-3)*c.srcLd], acc);
    if (t >= 2) acc = fmaf(w1, base[(size_t)(t-2)*c.srcLd], acc);
    if (t >= 1) acc = fmaf(w2, base[(size_t)(t-1)*c.srcLd], acc);
    acc = fmaf(w3, base[(size_t)t*c.srcLd], acc);
    c.dst[(size_t)r*DI + d] = acc / (1.f + __expf(-acc));
}

/* ---------------- big GEMM: 128x128 tile, 8x8/thread, dir-batched -------- */
__global__ void __launch_bounds__(256) gemm128(GArgs g0, GArgs g1,
                                               int lda, int ldc,
                                               int M, int N, int K, int act)
{
    GArgs g = blockIdx.z ? g1 : g0;
    __shared__ float As[16][132];
    __shared__ float Bs[16][132];
    const int tid = threadIdx.x;
    const int r0 = blockIdx.y * 128;
    const int c0 = blockIdx.x * 128;
    const int lr = tid >> 2;
    const int lc = (tid & 3) * 4;
    const int tx = tid & 15;
    const int ty = tid >> 4;

    const float* aP[2] = {nullptr, nullptr};
    const float* wP[2];
#pragma unroll
    for (int rr = 0; rr < 2; rr++) {
        int grow = r0 + lr + rr*64;
        if (grow < M) {
            int sr = grow;
            if (g.flipA) { int bb = grow / TSEQ; int tt = grow - bb*TSEQ; sr = bb*TSEQ + (TSEQ-1-tt); }
            aP[rr] = g.A + (size_t)sr*lda + lc;
        }
        wP[rr] = g.W + (size_t)(c0 + lr + rr*64)*K + lc;
    }

    float4 pa[2], pw[2];
#pragma unroll
    for (int rr = 0; rr < 2; rr++) {
        pa[rr] = aP[rr] ? *(const float4*)(aP[rr]) : make_float4(0,0,0,0);
        pw[rr] = *(const float4*)(wP[rr]);
    }

    float acc[8][8];
#pragma unroll
    for (int i = 0; i < 8; i++)
#pragma unroll
        for (int j = 0; j < 8; j++) acc[i][j] = 0.f;

    for (int k0 = 0; k0 < K; k0 += 16) {
        __syncthreads();
#pragma unroll
        for (int rr = 0; rr < 2; rr++) {
            As[lc+0][lr+rr*64] = pa[rr].x; As[lc+1][lr+rr*64] = pa[rr].y;
            As[lc+2][lr+rr*64] = pa[rr].z; As[lc+3][lr+rr*64] = pa[rr].w;
            Bs[lc+0][lr+rr*64] = pw[rr].x; Bs[lc+1][lr+rr*64] = pw[rr].y;
            Bs[lc+2][lr+rr*64] = pw[rr].z; Bs[lc+3][lr+rr*64] = pw[rr].w;
        }
        __syncthreads();
        if (k0 + 16 < K) {
#pragma unroll
            for (int rr = 0; rr < 2; rr++) {
                pa[rr] = aP[rr] ? *(const float4*)(aP[rr] + k0 + 16) : make_float4(0,0,0,0);
                pw[rr] = *(const float4*)(wP[rr] + k0 + 16);
            }
        }
#pragma unroll
        for (int kk = 0; kk < 16; kk++) {
            float4 a0 = *(const float4*)&As[kk][ty*4];
            float4 a1 = *(const float4*)&As[kk][64 + ty*4];
            float4 b0 = *(const float4*)&Bs[kk][tx*4];
            float4 b1 = *(const float4*)&Bs[kk][64 + tx*4];
            float av[8] = {a0.x,a0.y,a0.z,a0.w,a1.x,a1.y,a1.z,a1.w};
            float bv[8] = {b0.x,b0.y,b0.z,b0.w,b1.x,b1.y,b1.z,b1.w};
#pragma unroll
            for (int i = 0; i < 8; i++)
#pragma unroll
                for (int j = 0; j < 8; j++)
                    acc[i][j] = fmaf(av[i], bv[j], acc[i][j]);
        }
    }

#pragma unroll
    for (int i = 0; i < 8; i++) {
        int row = r0 + ((i < 4) ? 0 : 64) + ty*4 + (i & 3);
        if (row >= M) continue;
        int srow = row;
        if (g.flipC) { int bb = row / TSEQ; int tt = row - bb*TSEQ; srow = bb*TSEQ + (TSEQ-1-tt); }
        float* crow = g.C + (size_t)srow*ldc;
        const float* rrow = g.res ? g.res + (size_t)srow*ldc : nullptr;
#pragma unroll
        for (int j = 0; j < 8; j++) {
            int col = c0 + ((j < 4) ? 0 : 64) + tx*4 + (j & 3);
            float v = acc[i][j];
            if (g.bias) v += g.bias[col];
            if (act == 1) v = fmaxf(v, 0.f) + log1pf(__expf(-fabsf(v)));
            if (rrow) v += rrow[col];
            crow[col] = v;
        }
    }
}

/* ---------------- small GEMM (128x64 tile), dir-batched ---------------- */
__global__ void __launch_bounds__(256) gemm_kernel(GArgs g0, GArgs g1,
                                                   int lda, int ldc,
                                                   int Mm, int Nn, int K, int act)
{
    GArgs g = blockIdx.z ? g1 : g0;
    __shared__ float As[16][128];
    __shared__ float Bs[16][64];
    const int tid = threadIdx.x;
    const int r0 = blockIdx.y * 128;
    const int c0 = blockIdx.x * 64;
    const int tm = tid & 15;
    const int tn = tid >> 4;
    const int a4 = tid & 3;
    const int ar = tid >> 2;

    const float* aptr0 = nullptr;
    const float* aptr1 = nullptr;
    {
        int grow = r0 + ar;
        if (grow < Mm) {
            int sr = grow;
            if (g.flipA) { int bb = grow / TSEQ; int tt = grow - bb*TSEQ; sr = bb*TSEQ + (TSEQ-1-tt); }
            aptr0 = g.A + (size_t)sr*lda + a4*4;
        }
        grow = r0 + ar + 64;
        if (grow < Mm) {
            int sr = grow;
            if (g.flipA) { int bb = grow / TSEQ; int tt = grow - bb*TSEQ; sr = bb*TSEQ + (TSEQ-1-tt); }
            aptr1 = g.A + (size_t)sr*lda + a4*4;
        }
    }
    const float* wptr = g.W + (size_t)(c0 + ar)*K + a4*4;

    float4 pa0 = aptr0 ? *(const float4*)(aptr0) : make_float4(0,0,0,0);
    float4 pa1 = aptr1 ? *(const float4*)(aptr1) : make_float4(0,0,0,0);
    float4 pw  = *(const float4*)(wptr);

    float acc[8][4];
#pragma unroll
    for (int i = 0; i < 8; i++)
#pragma unroll
        for (int j = 0; j < 4; j++) acc[i][j] = 0.f;

    for (int k0 = 0; k0 < K; k0 += 16) {
        __syncthreads();
        As[a4*4+0][ar]    = pa0.x; As[a4*4+1][ar]    = pa0.y;
        As[a4*4+2][ar]    = pa0.z; As[a4*4+3][ar]    = pa0.w;
        As[a4*4+0][ar+64] = pa1.x; As[a4*4+1][ar+64] = pa1.y;
        As[a4*4+2][ar+64] = pa1.z; As[a4*4+3][ar+64] = pa1.w;
        Bs[a4*4+0][ar]    = pw.x;  Bs[a4*4+1][ar]    = pw.y;
        Bs[a4*4+2][ar]    = pw.z;  Bs[a4*4+3][ar]    = pw.w;
        __syncthreads();
        if (k0 + 16 < K) {
            pa0 = aptr0 ? *(const float4*)(aptr0 + k0 + 16) : make_float4(0,0,0,0);
            pa1 = aptr1 ? *(const float4*)(aptr1 + k0 + 16) : make_float4(0,0,0,0);
            pw  = *(const float4*)(wptr + k0 + 16);
        }
#pragma unroll
        for (int kk = 0; kk < 16; kk++) {
            float4 b4 = *(const float4*)&Bs[kk][tn*4];
            float4 a0 = *(const float4*)&As[kk][tm*8];
            float4 a1 = *(const float4*)&As[kk][tm*8+4];
            float av[8] = {a0.x,a0.y,a0.z,a0.w,a1.x,a1.y,a1.z,a1.w};
            float bv[4] = {b4.x,b4.y,b4.z,b4.w};
#pragma unroll
            for (int i = 0; i < 8; i++)
#pragma unroll
                for (int j = 0; j < 4; j++)
                    acc[i][j] = fmaf(av[i], bv[j], acc[i][j]);
        }
    }

#pragma unroll
    for (int i = 0; i < 8; i++) {
        int row = r0 + tm*8 + i;
        if (row >= Mm) continue;
        int srow = row;
        if (g.flipC) { int bb = row / TSEQ; int tt = row - bb*TSEQ; srow = bb*TSEQ + (TSEQ-1-tt); }
        float* crow = g.C + (size_t)srow*ldc;
        const float* rrow = g.res ? g.res + (size_t)srow*ldc : nullptr;
#pragma unroll
        for (int j = 0; j < 4; j++) {
            int col = c0 + tn*4 + j;
            if (col >= Nn) continue;
            float v = acc[i][j];
            if (g.bias) v += g.bias[col];
            if (act == 1) v = fmaxf(v, 0.f) + log1pf(__expf(-fabsf(v)));
            if (rrow) v += rrow[col];
            crow[col] = v;
        }
    }
}

/* ---------------- selective scan, dir-batched, prefetch-4 ---------------- */
__global__ void __launch_bounds__(128) scan_kernel(const float* __restrict__ Al0,
                                                   const float* __restrict__ Al1,
                                                   const float* __restrict__ Dp0,
                                                   const float* __restrict__ Dp1)
{
    const int z   = blockIdx.z;
    const float* Al = z ? Al1 : Al0;
    const float* Dp = z ? Dp1 : Dp0;
    const int b   = blockIdx.x;
    const int tid = threadIdx.x;
    const int dl  = tid >> 4;
    const int n   = tid & 15;
    const int d   = blockIdx.y*8 + dl;

    const float Adn = -__expf(Al[d*NSTATE + n]);
    const float Dpd = Dp[d];
    float h = 0.f;

    const float* dptr = g_DELTA[z] + (size_t)b*TSEQ*DI + d;
    const float* uptr = g_XM[z]    + (size_t)b*TSEQ*DI + d;
    const float* pptr = g_PROJ[z]  + (size_t)b*TSEQ*64;
    const float* zptr = g_T2[z]    + (size_t)b*TSEQ*1024 + 512 + d;
    float*       yptr = g_YM[z]    + (size_t)b*TSEQ*DI + d;

    for (int t0 = 0; t0 < TSEQ; t0 += 4) {
        float dv[4], uv[4], bv[4], cv[4], zv[4];
#pragma unroll
        for (int i = 0; i < 4; i++) {
            int t = t0 + i;
            if (t < TSEQ) {
                dv[i] = __ldg(dptr + (size_t)t*DI);
                uv[i] = __ldg(uptr + (size_t)t*DI);
                bv[i] = __ldg(pptr + t*64 + 32 + n);
                cv[i] = __ldg(pptr + t*64 + 48 + n);
                zv[i] = __ldg(zptr + (size_t)t*1024);
            }
        }
#pragma unroll
        for (int i = 0; i < 4; i++) {
            int t = t0 + i;
            if (t < TSEQ) {
                float dA = __expf(dv[i] * Adn);
                h = fmaf(dA, h, dv[i] * bv[i] * uv[i]);
                float v = h * cv[i];
                v += __shfl_xor_sync(0xffffffffu, v, 1);
                v += __shfl_xor_sync(0xffffffffu, v, 2);
                v += __shfl_xor_sync(0xffffffffu, v, 4);
                v += __shfl_xor_sync(0xffffffffu, v, 8);
                if (n == 0) {
                    float zz = zv[i];
                    float y = fmaf(uv[i], Dpd, v);
                    yptr[(size_t)t*DI] = y * (zz / (1.f + __expf(-zz)));
                }
            }
        }
    }
}

/* ---------------- gate + concat ---------------- */
__global__ void gate_kernel()
{
    int idx = blockIdx.x*blockDim.x + threadIdx.x;
    if (idx >= MROWS*DI) return;
    int d = idx & 511;
    int r = idx >> 9;
    float rv = g_TMP[(size_t)r*1024 + 512 + d];
    float gate = rv / (1.f + __expf(-rv));
    g_G[(size_t)r*1024 + d]       = g_YF[(size_t)r*DI + d] * gate;
    g_G[(size_t)r*1024 + 512 + d] = g_YB[(size_t)r*DI + d] * gate;
}

/* ---------------- final LN on the cls row ---------------- */
__global__ void final_kernel(const float* __restrict__ g,
                             const float* __restrict__ bt,
                             float* __restrict__ out)
{
    __shared__ float s1[8], s2[8];
    int b = blockIdx.x;
    int c = threadIdx.x;
    float v = g_X[((size_t)b*TSEQ)*DM + c];
    float s = v, ss = v*v;
#pragma unroll
    for (int o = 16; o; o >>= 1) {
        s  += __shfl_xor_sync(0xffffffffu, s,  o);
        ss += __shfl_xor_sync(0xffffffffu, ss, o);
    }
    int w = c >> 5, l = c & 31;
    if (l == 0) { s1[w] = s; s2[w] = ss; }
    __syncthreads();
    float ts = 0.f, tss = 0.f;
#pragma unroll
    for (int i = 0; i < 8; i++) { ts += s1[i]; tss += s2[i]; }
    float mean = ts * (1.f/256.f);
    float var  = tss * (1.f/256.f) - mean*mean;
    out[b*DM + c] = (v-mean)*rsqrtf(var + 1e-5f)*g[c] + bt[c];
}

/* ======================= host driver ======================= */
extern "C" void kernel_launch(void* const* d_in, const int* in_sizes, int n_in,
                              void* d_out, int out_size)
{
    (void)in_sizes; (void)n_in; (void)out_size;
    const float* x       = (const float*)d_in[0];
    const float* patch_w = (const float*)d_in[1];
    const float* patch_b = (const float*)d_in[2];
    const float* cls_tok = (const float*)d_in[3];
    const float* ln_g    = (const float*)d_in[4];
    const float* ln_b    = (const float*)d_in[5];
    const float* in_w    = (const float*)d_in[6];
    const float* cw      = (const float*)d_in[7];
    const float* cb      = (const float*)d_in[8];
    const float* out_w   = (const float*)d_in[9];
    const float* fn_g    = (const float*)d_in[10];
    const float* fn_b    = (const float*)d_in[11];
    const float* m_in[2]  = {(const float*)d_in[12], (const float*)d_in[21]};
    const float* m_cw[2]  = {(const float*)d_in[13], (const float*)d_in[22]};
    const float* m_cb[2]  = {(const float*)d_in[14], (const float*)d_in[23]};
    const float* m_xp[2]  = {(const float*)d_in[15], (const float*)d_in[24]};
    const float* m_dtw[2] = {(const float*)d_in[16], (const float*)d_in[25]};
    const float* m_dtb[2] = {(const float*)d_in[17], (const float*)d_in[26]};
    const float* m_Al[2]  = {(const float*)d_in[18], (const float*)d_in[27]};
    const float* m_D[2]   = {(const float*)d_in[19], (const float*)d_in[28]};
    const float* m_ow[2]  = {(const float*)d_in[20], (const float*)d_in[29]};

    float *pX, *pXN, *pTMP, *pXC, *pT2, *pXM, *pPROJ, *pDELTA, *pYM, *pYF, *pYB, *pG;
    cudaGetSymbolAddress((void**)&pX,     g_X);
    cudaGetSymbolAddress((void**)&pXN,    g_XN);
    cudaGetSymbolAddress((void**)&pTMP,   g_TMP);
    cudaGetSymbolAddress((void**)&pXC,    g_XC);
    cudaGetSymbolAddress((void**)&pT2,    g_T2);
    cudaGetSymbolAddress((void**)&pXM,    g_XM);
    cudaGetSymbolAddress((void**)&pPROJ,  g_PROJ);
    cudaGetSymbolAddress((void**)&pDELTA, g_DELTA);
    cudaGetSymbolAddress((void**)&pYM,    g_YM);
    cudaGetSymbolAddress((void**)&pYF,    g_YF);
    cudaGetSymbolAddress((void**)&pYB,    g_YB);
    cudaGetSymbolAddress((void**)&pG,     g_G);

    patch_kernel<<<dim3(84, BATCH), 256>>>(x, patch_w, patch_b);
    cls_kernel<<<1, 1024>>>(cls_tok);

    for (int l = 0; l < 8; l++) {
        ln_kernel<<<251, 256>>>(pX, ln_g + l*DM, ln_b + l*DM, pXN, MROWS);

        {   /* in-proj: (2004x256)@(256x1024) -> TMP */
            GArgs a{pXN, in_w + (size_t)l*1024*DM, pTMP, nullptr, nullptr, 0, 0};
            gemm128<<<dim3(8, 16, 1), 256>>>(a, a, DM, 1024, MROWS, 1024, DM, 0);
        }
        {
            CArgs c{pTMP, 1024, cw + l*DI*4, cb + l*DI, pXC};
            conv_silu_kernel<<<dim3(4008, 1, 1), 256>>>(c, c);
        }
        {   /* mamba in-proj, both dirs */
            GArgs a0{pXC, m_in[0] + (size_t)l*1024*DI, pT2,               nullptr, nullptr, 0, 0};
            GArgs a1{pXC, m_in[1] + (size_t)l*1024*DI, pT2 + MROWS*1024,  nullptr, nullptr, 1, 0};
            gemm128<<<dim3(8, 16, 2), 256>>>(a0, a1, DI, 1024, MROWS, 1024, DI, 0);
        }
        {
            CArgs c0{pT2,              1024, m_cw[0] + l*DI*4, m_cb[0] + l*DI, pXM};
            CArgs c1{pT2 + MROWS*1024, 1024, m_cw[1] + l*DI*4, m_cb[1] + l*DI, pXM + MROWS*DI};
            conv_silu_kernel<<<dim3(4008, 1, 2), 256>>>(c0, c1);
        }
        {   /* x-proj -> [dt(32) | B(16) | C(16)] */
            GArgs a0{pXM,            m_xp[0] + (size_t)l*64*DI, pPROJ,            nullptr, nullptr, 0, 0};
            GArgs a1{pXM + MROWS*DI, m_xp[1] + (size_t)l*64*DI, pPROJ + MROWS*64, nullptr, nullptr, 0, 0};
            gemm_kernel<<<dim3(1, 16, 2), 256>>>(a0, a1, DI, 64, MROWS, 64, DI, 0);
        }
        {   /* dt-proj + softplus */
            GArgs a0{pPROJ,            m_dtw[0] + (size_t)l*DI*32, pDELTA,            m_dtb[0] + l*DI, nullptr, 0, 0};
            GArgs a1{pPROJ + MROWS*64, m_dtw[1] + (size_t)l*DI*32, pDELTA + MROWS*DI, m_dtb[1] + l*DI, nullptr, 0, 0};
            gemm_kernel<<<dim3(8, 16, 2), 256>>>(a0, a1, 64, DI, MROWS, DI, 32, 1);
        }
        scan_kernel<<<dim3(BATCH, 64, 2), 128>>>(m_Al[0] + (size_t)l*DI*NSTATE,
                                                 m_Al[1] + (size_t)l*DI*NSTATE,
                                                 m_D[0] + l*DI, m_D[1] + l*DI);
        {   /* mamba out-proj (z=1 un-flips rows on store) */
            GArgs a0{pYM,            m_ow[0] + (size_t)l*DI*DI, pYF, nullptr, nullptr, 0, 0};
            GArgs a1{pYM + MROWS*DI, m_ow[1] + (size_t)l*DI*DI, pYB, nullptr, nullptr, 0, 1};
            gemm128<<<dim3(4, 16, 2), 256>>>(a0, a1, DI, DI, MROWS, DI, DI, 0);
        }
        gate_kernel<<<4008, 256>>>();
        {   /* block out-proj + residual: X = G@out_w^T + X */
            GArgs a{pG, out_w + (size_t)l*DM*1024, pX, nullptr, pX, 0, 0};
            gemm_kernel<<<dim3(4, 16, 1), 256>>>(a, a, 1024, DM, MROWS, DM, 1024, 0);
        }
    }
    final_kernel<<<BATCH, 256>>>(fn_g, fn_b, (float*)d_out);
}

// round 8
// speedup vs baseline: 2.4343x; 1.1194x over previous
#include <cuda_runtime.h>
#include <math.h>

#define BATCH 4
#define TSEQ 501
#define MROWS (BATCH*TSEQ)   /* 2004 */
#define DM 256
#define DI 512
#define NSTATE 16

/* ---------------- persistent scratch (no allocs allowed) ---------------- */
__device__ __align__(256) float g_X    [MROWS*DM];
__device__ __align__(256) float g_XN   [MROWS*DM];
__device__ __align__(256) float g_TMP  [MROWS*1024];
__device__ __align__(256) float g_XC   [MROWS*DI];
__device__ __align__(256) float g_T2   [2][MROWS*1024];
__device__ __align__(256) float g_XM   [2][MROWS*DI];
__device__ __align__(256) float g_PROJ [2][MROWS*64];
__device__ __align__(256) float g_DELTA[2][MROWS*DI];
__device__ __align__(256) float g_YM   [2][MROWS*DI];
__device__ __align__(256) float g_G    [MROWS*1024];

/* ---------------- per-direction argument bundles ---------------- */
struct GArgs {
    const float* A;
    const float* W;
    float*       C;
    const float* bias;
    const float* res;    /* residual add, stride ldc            */
    const float* gate;   /* silu-gate source, stride 1024       */
    int flipA;
    int flipC;
};

struct CArgs {
    const float* src;
    int          srcLd;
    const float* cw;
    const float* cb;
    float*       dst;
};

/* ---------------- patch embedding: conv1d k=10 stride=10 ---------------- */
#define PPT 6
__global__ void __launch_bounds__(256) patch_kernel(const float* __restrict__ x,
                                                    const float* __restrict__ pw,
                                                    const float* __restrict__ pb)
{
    __shared__ float xs[129*PPT*10];
    __shared__ float ws[256*10];
    const int bb  = blockIdx.y;
    const int pp0 = blockIdx.x * PPT;
    const int tid = threadIdx.x;
    const int t0  = pp0 * 10;

    for (int e = tid; e < 129*PPT*10; e += 256) {
        int i   = e / (PPT*10);
        int off = e - i*(PPT*10);
        int ta  = t0 + off;
        xs[e] = (ta < 5000) ? x[((size_t)bb*129 + i)*5000 + ta] : 0.f;
    }

    const int c = tid;
    float acc[PPT];
#pragma unroll
    for (int p = 0; p < PPT; p++) acc[p] = pb[c];

    for (int i = 0; i < 129; i++) {
        __syncthreads();
        for (int e = tid; e < 2560; e += 256) {
            int cc = e / 10;
            int kk = e - cc*10;
            ws[e] = pw[(size_t)cc*1290 + i*10 + kk];
        }
        __syncthreads();
#pragma unroll
        for (int k = 0; k < 10; k++) {
            float wv = ws[c*10 + k];
            const float* xrow = &xs[i*(PPT*10) + k];
#pragma unroll
            for (int p = 0; p < PPT; p++)
                acc[p] = fmaf(wv, xrow[p*10], acc[p]);
        }
    }
#pragma unroll
    for (int p = 0; p < PPT; p++) {
        int pp = pp0 + p;
        if (pp < 500)
            g_X[((size_t)bb*TSEQ + 1 + pp)*DM + c] = acc[p];
    }
}

__global__ void cls_kernel(const float* __restrict__ cls)
{
    int tid = threadIdx.x;
    int b = tid >> 8, c = tid & 255;
    g_X[((size_t)b*TSEQ)*DM + c] = cls[c];
}

/* ---------------- layernorm over 256 (warp per row) ---------------- */
__global__ void ln_kernel(const float* __restrict__ Xin,
                          const float* __restrict__ g,
                          const float* __restrict__ bt,
                          float* __restrict__ Out, int rows)
{
    int warp = (blockIdx.x * blockDim.x + threadIdx.x) >> 5;
    int lane = threadIdx.x & 31;
    if (warp >= rows) return;
    const float* xr = Xin + (size_t)warp*DM;
    float v[8], s = 0.f, ss = 0.f;
#pragma unroll
    for (int i = 0; i < 8; i++) {
        v[i] = xr[lane + i*32];
        s += v[i];
        ss = fmaf(v[i], v[i], ss);
    }
#pragma unroll
    for (int o = 16; o; o >>= 1) {
        s  += __shfl_xor_sync(0xffffffffu, s,  o);
        ss += __shfl_xor_sync(0xffffffffu, ss, o);
    }
    float mean = s * (1.f/256.f);
    float var  = ss * (1.f/256.f) - mean*mean;
    float inv  = rsqrtf(var + 1e-5f);
    float* orow = Out + (size_t)warp*DM;
#pragma unroll
    for (int i = 0; i < 8; i++) {
        int c = lane + i*32;
        orow[c] = (v[i]-mean)*inv*g[c] + bt[c];
    }
}

/* ---------------- causal depthwise conv (K=4) + silu, dir-batched -------- */
__global__ void conv_silu_kernel(CArgs c0, CArgs c1)
{
    CArgs c = blockIdx.z ? c1 : c0;
    int idx = blockIdx.x*blockDim.x + threadIdx.x;
    if (idx >= MROWS*DI) return;
    int d = idx & 511;
    int r = idx >> 9;
    int t = r % TSEQ;
    int b = r / TSEQ;
    const float* base = c.src + ((size_t)b*TSEQ)*c.srcLd + d;
    float acc = c.cb[d];
    float w0 = c.cw[d*4+0], w1 = c.cw[d*4+1], w2 = c.cw[d*4+2], w3 = c.cw[d*4+3];
    if (t >= 3) acc = fmaf(w0, base[(size_t)(t-3)*c.srcLd], acc);
    if (t >= 2) acc = fmaf(w1, base[(size_t)(t-2)*c.srcLd], acc);
    if (t >= 1) acc = fmaf(w2, base[(size_t)(t-1)*c.srcLd], acc);
    acc = fmaf(w3, base[(size_t)t*c.srcLd], acc);
    c.dst[(size_t)r*DI + d] = acc / (1.f + __expf(-acc));
}

/* ---------------- unified GEMM: 128x64 tile, 8x4/thread, dir-batched ------
 * C = act(A@W^T + bias) [* silu(gate)] [+ res]
 * A: M x K (lda), W: N x K row-major, C: M x N (ldc). N multiple of 64,
 * K multiple of 16. flipA/flipC flip the time index within each batch.
 */
__global__ void __launch_bounds__(256, 3) gemmT(GArgs g0, GArgs g1,
                                                int lda, int ldc,
                                                int M, int K, int act)
{
    GArgs g = blockIdx.z ? g1 : g0;
    __shared__ float As[16][132];
    __shared__ float Bs[16][68];
    const int tid = threadIdx.x;
    const int r0 = blockIdx.y * 128;
    const int c0 = blockIdx.x * 64;
    const int lr = tid >> 2;        /* 0..63                 */
    const int lc = (tid & 3) * 4;   /* k-offset within tile  */
    const int tx = tid & 15;        /* col group: 4 cols     */
    const int ty = tid >> 4;        /* row group: 8 rows     */

    const float* aP[2] = {nullptr, nullptr};
#pragma unroll
    for (int rr = 0; rr < 2; rr++) {
        int grow = r0 + lr + rr*64;
        if (grow < M) {
            int sr = grow;
            if (g.flipA) { int bb = grow / TSEQ; int tt = grow - bb*TSEQ; sr = bb*TSEQ + (TSEQ-1-tt); }
            aP[rr] = g.A + (size_t)sr*lda + lc;
        }
    }
    const float* wP = g.W + (size_t)(c0 + lr)*K + lc;

    float4 pa[2], pw;
#pragma unroll
    for (int rr = 0; rr < 2; rr++)
        pa[rr] = aP[rr] ? *(const float4*)(aP[rr]) : make_float4(0,0,0,0);
    pw = *(const float4*)(wP);

    float acc[8][4];
#pragma unroll
    for (int i = 0; i < 8; i++)
#pragma unroll
        for (int j = 0; j < 4; j++) acc[i][j] = 0.f;

    for (int k0 = 0; k0 < K; k0 += 16) {
        __syncthreads();
#pragma unroll
        for (int rr = 0; rr < 2; rr++) {
            As[lc+0][lr+rr*64] = pa[rr].x; As[lc+1][lr+rr*64] = pa[rr].y;
            As[lc+2][lr+rr*64] = pa[rr].z; As[lc+3][lr+rr*64] = pa[rr].w;
        }
        Bs[lc+0][lr] = pw.x; Bs[lc+1][lr] = pw.y;
        Bs[lc+2][lr] = pw.z; Bs[lc+3][lr] = pw.w;
        __syncthreads();
        if (k0 + 16 < K) {
#pragma unroll
            for (int rr = 0; rr < 2; rr++)
                pa[rr] = aP[rr] ? *(const float4*)(aP[rr] + k0 + 16) : make_float4(0,0,0,0);
            pw = *(const float4*)(wP + k0 + 16);
        }
#pragma unroll
        for (int kk = 0; kk < 16; kk++) {
            float4 a0 = *(const float4*)&As[kk][ty*8];
            float4 a1 = *(const float4*)&As[kk][ty*8+4];
            float4 b0 = *(const float4*)&Bs[kk][tx*4];
            float av[8] = {a0.x,a0.y,a0.z,a0.w,a1.x,a1.y,a1.z,a1.w};
            float bv[4] = {b0.x,b0.y,b0.z,b0.w};
#pragma unroll
            for (int i = 0; i < 8; i++)
#pragma unroll
                for (int j = 0; j < 4; j++)
                    acc[i][j] = fmaf(av[i], bv[j], acc[i][j]);
        }
    }

#pragma unroll
    for (int i = 0; i < 8; i++) {
        int row = r0 + ty*8 + i;
        if (row >= M) continue;
        int srow = row;
        if (g.flipC) { int bb = row / TSEQ; int tt = row - bb*TSEQ; srow = bb*TSEQ + (TSEQ-1-tt); }
        float* crow = g.C + (size_t)srow*ldc;
        const float* rrow = g.res  ? g.res  + (size_t)srow*ldc   : nullptr;
        const float* grow = g.gate ? g.gate + (size_t)srow*1024  : nullptr;
#pragma unroll
        for (int j = 0; j < 4; j++) {
            int col = c0 + tx*4 + j;
            float v = acc[i][j];
            if (g.bias) v += g.bias[col];
            if (act == 1) v = fmaxf(v, 0.f) + log1pf(__expf(-fabsf(v)));
            if (grow) { float gv = grow[col]; v *= gv / (1.f + __expf(-gv)); }
            if (rrow) v += rrow[col];
            crow[col] = v;
        }
    }
}

/* ---------------- selective scan, dir-batched, prefetch-4 ---------------- */
__global__ void __launch_bounds__(128) scan_kernel(const float* __restrict__ Al0,
                                                   const float* __restrict__ Al1,
                                                   const float* __restrict__ Dp0,
                                                   const float* __restrict__ Dp1)
{
    const int z   = blockIdx.z;
    const float* Al = z ? Al1 : Al0;
    const float* Dp = z ? Dp1 : Dp0;
    const int b   = blockIdx.x;
    const int tid = threadIdx.x;
    const int dl  = tid >> 4;
    const int n   = tid & 15;
    const int d   = blockIdx.y*8 + dl;

    const float Adn = -__expf(Al[d*NSTATE + n]);
    const float Dpd = Dp[d];
    float h = 0.f;

    const float* dptr = g_DELTA[z] + (size_t)b*TSEQ*DI + d;
    const float* uptr = g_XM[z]    + (size_t)b*TSEQ*DI + d;
    const float* pptr = g_PROJ[z]  + (size_t)b*TSEQ*64;
    const float* zptr = g_T2[z]    + (size_t)b*TSEQ*1024 + 512 + d;
    float*       yptr = g_YM[z]    + (size_t)b*TSEQ*DI + d;

    for (int t0 = 0; t0 < TSEQ; t0 += 4) {
        float dv[4], uv[4], bv[4], cv[4], zv[4];
#pragma unroll
        for (int i = 0; i < 4; i++) {
            int t = t0 + i;
            if (t < TSEQ) {
                dv[i] = __ldg(dptr + (size_t)t*DI);
                uv[i] = __ldg(uptr + (size_t)t*DI);
                bv[i] = __ldg(pptr + t*64 + 32 + n);
                cv[i] = __ldg(pptr + t*64 + 48 + n);
                zv[i] = __ldg(zptr + (size_t)t*1024);
            }
        }
#pragma unroll
        for (int i = 0; i < 4; i++) {
            int t = t0 + i;
            if (t < TSEQ) {
                float dA = __expf(dv[i] * Adn);
                h = fmaf(dA, h, dv[i] * bv[i] * uv[i]);
                float v = h * cv[i];
                v += __shfl_xor_sync(0xffffffffu, v, 1);
                v += __shfl_xor_sync(0xffffffffu, v, 2);
                v += __shfl_xor_sync(0xffffffffu, v, 4);
                v += __shfl_xor_sync(0xffffffffu, v, 8);
                if (n == 0) {
                    float zz = zv[i];
                    float y = fmaf(uv[i], Dpd, v);
                    yptr[(size_t)t*DI] = y * (zz / (1.f + __expf(-zz)));
                }
            }
        }
    }
}

/* ---------------- final LN on the cls row ---------------- */
__global__ void final_kernel(const float* __restrict__ g,
                             const float* __restrict__ bt,
                             float* __restrict__ out)
{
    __shared__ float s1[8], s2[8];
    int b = blockIdx.x;
    int c = threadIdx.x;
    float v = g_X[((size_t)b*TSEQ)*DM + c];
    float s = v, ss = v*v;
#pragma unroll
    for (int o = 16; o; o >>= 1) {
        s  += __shfl_xor_sync(0xffffffffu, s,  o);
        ss += __shfl_xor_sync(0xffffffffu, ss, o);
    }
    int w = c >> 5, l = c & 31;
    if (l == 0) { s1[w] = s; s2[w] = ss; }
    __syncthreads();
    float ts = 0.f, tss = 0.f;
#pragma unroll
    for (int i = 0; i < 8; i++) { ts += s1[i]; tss += s2[i]; }
    float mean = ts * (1.f/256.f);
    float var  = tss * (1.f/256.f) - mean*mean;
    out[b*DM + c] = (v-mean)*rsqrtf(var + 1e-5f)*g[c] + bt[c];
}

/* ======================= host driver ======================= */
extern "C" void kernel_launch(void* const* d_in, const int* in_sizes, int n_in,
                              void* d_out, int out_size)
{
    (void)in_sizes; (void)n_in; (void)out_size;
    const float* x       = (const float*)d_in[0];
    const float* patch_w = (const float*)d_in[1];
    const float* patch_b = (const float*)d_in[2];
    const float* cls_tok = (const float*)d_in[3];
    const float* ln_g    = (const float*)d_in[4];
    const float* ln_b    = (const float*)d_in[5];
    const float* in_w    = (const float*)d_in[6];
    const float* cw      = (const float*)d_in[7];
    const float* cb      = (const float*)d_in[8];
    const float* out_w   = (const float*)d_in[9];
    const float* fn_g    = (const float*)d_in[10];
    const float* fn_b    = (const float*)d_in[11];
    const float* m_in[2]  = {(const float*)d_in[12], (const float*)d_in[21]};
    const float* m_cw[2]  = {(const float*)d_in[13], (const float*)d_in[22]};
    const float* m_cb[2]  = {(const float*)d_in[14], (const float*)d_in[23]};
    const float* m_xp[2]  = {(const float*)d_in[15], (const float*)d_in[24]};
    const float* m_dtw[2] = {(const float*)d_in[16], (const float*)d_in[25]};
    const float* m_dtb[2] = {(const float*)d_in[17], (const float*)d_in[26]};
    const float* m_Al[2]  = {(const float*)d_in[18], (const float*)d_in[27]};
    const float* m_D[2]   = {(const float*)d_in[19], (const float*)d_in[28]};
    const float* m_ow[2]  = {(const float*)d_in[20], (const float*)d_in[29]};

    float *pX, *pXN, *pTMP, *pXC, *pT2, *pXM, *pPROJ, *pDELTA, *pYM, *pG;
    cudaGetSymbolAddress((void**)&pX,     g_X);
    cudaGetSymbolAddress((void**)&pXN,    g_XN);
    cudaGetSymbolAddress((void**)&pTMP,   g_TMP);
    cudaGetSymbolAddress((void**)&pXC,    g_XC);
    cudaGetSymbolAddress((void**)&pT2,    g_T2);
    cudaGetSymbolAddress((void**)&pXM,    g_XM);
    cudaGetSymbolAddress((void**)&pPROJ,  g_PROJ);
    cudaGetSymbolAddress((void**)&pDELTA, g_DELTA);
    cudaGetSymbolAddress((void**)&pYM,    g_YM);
    cudaGetSymbolAddress((void**)&pG,     g_G);

    patch_kernel<<<dim3(84, BATCH), 256>>>(x, patch_w, patch_b);
    cls_kernel<<<1, 1024>>>(cls_tok);

    for (int l = 0; l < 8; l++) {
        ln_kernel<<<251, 256>>>(pX, ln_g + l*DM, ln_b + l*DM, pXN, MROWS);

        {   /* in-proj: (2004x256)@(256x1024) -> TMP  (256 blocks) */
            GArgs a{pXN, in_w + (size_t)l*1024*DM, pTMP, nullptr, nullptr, nullptr, 0, 0};
            gemmT<<<dim3(16, 16, 1), 256>>>(a, a, DM, 1024, MROWS, DM, 0);
        }
        {
            CArgs c{pTMP, 1024, cw + l*DI*4, cb + l*DI, pXC};
            conv_silu_kernel<<<dim3(4008, 1, 1), 256>>>(c, c);
        }
        {   /* mamba in-proj, both dirs (512 blocks) */
            GArgs a0{pXC, m_in[0] + (size_t)l*1024*DI, pT2,              nullptr, nullptr, nullptr, 0, 0};
            GArgs a1{pXC, m_in[1] + (size_t)l*1024*DI, pT2 + MROWS*1024, nullptr, nullptr, nullptr, 1, 0};
            gemmT<<<dim3(16, 16, 2), 256>>>(a0, a1, DI, 1024, MROWS, DI, 0);
        }
        {
            CArgs c0{pT2,              1024, m_cw[0] + l*DI*4, m_cb[0] + l*DI, pXM};
            CArgs c1{pT2 + MROWS*1024, 1024, m_cw[1] + l*DI*4, m_cb[1] + l*DI, pXM + MROWS*DI};
            conv_silu_kernel<<<dim3(4008, 1, 2), 256>>>(c0, c1);
        }
        {   /* x-proj -> [dt(32) | B(16) | C(16)]  (32 blocks) */
            GArgs a0{pXM,            m_xp[0] + (size_t)l*64*DI, pPROJ,            nullptr, nullptr, nullptr, 0, 0};
            GArgs a1{pXM + MROWS*DI, m_xp[1] + (size_t)l*64*DI, pPROJ + MROWS*64, nullptr, nullptr, nullptr, 0, 0};
            gemmT<<<dim3(1, 16, 2), 256>>>(a0, a1, DI, 64, MROWS, DI, 0);
        }
        {   /* dt-proj + softplus  (256 blocks) */
            GArgs a0{pPROJ,            m_dtw[0] + (size_t)l*DI*32, pDELTA,            m_dtb[0] + l*DI, nullptr, nullptr, 0, 0};
            GArgs a1{pPROJ + MROWS*64, m_dtw[1] + (size_t)l*DI*32, pDELTA + MROWS*DI, m_dtb[1] + l*DI, nullptr, nullptr, 0, 0};
            gemmT<<<dim3(8, 16, 2), 256>>>(a0, a1, 64, DI, MROWS, 32, 1);
        }
        scan_kernel<<<dim3(BATCH, 64, 2), 128>>>(m_Al[0] + (size_t)l*DI*NSTATE,
                                                 m_Al[1] + (size_t)l*DI*NSTATE,
                                                 m_D[0] + l*DI, m_D[1] + l*DI);
        {   /* mamba out-proj fused with silu(res) gate -> concat G (256 blocks)
             * forward -> G[:, 0:512), backward (un-flip rows) -> G[:, 512:1024) */
            GArgs a0{pYM,            m_ow[0] + (size_t)l*DI*DI, pG,       nullptr, nullptr, pTMP + 512, 0, 0};
            GArgs a1{pYM + MROWS*DI, m_ow[1] + (size_t)l*DI*DI, pG + 512, nullptr, nullptr, pTMP + 512, 0, 1};
            gemmT<<<dim3(8, 16, 2), 256>>>(a0, a1, DI, 1024, MROWS, DI, 0);
        }
        {   /* block out-proj + residual: X = G@out_w^T + X  (64 blocks) */
            GArgs a{pG, out_w + (size_t)l*DM*1024, pX, nullptr, pX, nullptr, 0, 0};
            gemmT<<<dim3(4, 16, 1), 256>>>(a, a, 1024, DM, MROWS, 1024, 0);
        }
    }
    final_kernel<<<BATCH, 256>>>(fn_g, fn_b, (float*)d_out);
}